// round 8
// baseline (speedup 1.0000x reference)
#include <cuda_runtime.h>
#include <cuda_bf16.h>
#include <stdint.h>

// ----------------------------------------------------------------------------
// VQExpert via mma.sync bf16 (base ISA -> compiles for compute_103).
// bf16x3 split with shared-operand tiles: per k-tile load Ah,Al,Bh,Bl once,
// accumulate dot = Ah*Bh + Al*Bh + Ah*Bl (fp32 accum; AlBl dropped ~2e-6).
// dist = (zsq + esq) - 2*dot, fused per-row argmin, then gather + loss.
// R8: CTA 256x256, 512 threads, warp tile 64x64 (ratio 6 MMA/LDSM).
// ----------------------------------------------------------------------------

#define KDIM 512
#define MDIM 32768
#define NDIM 8192
#define BM 256
#define BN 256
#define BK 32
#define STAGES 3
#define NKT (KDIM / BK)        // 16
// stage regions (each 256*32*2 = 16KB): Ah | Al | Bh | Bl ; stage = 64KB
#define R_AL 16384
#define R_BH 32768
#define R_BL 49152
#define STG  65536
#define SMEM_DYN (STAGES * STG)   // 196608

__device__ __align__(16) __nv_bfloat16 g_Ah[(size_t)MDIM * KDIM];
__device__ __align__(16) __nv_bfloat16 g_Al[(size_t)MDIM * KDIM];
__device__ __align__(16) __nv_bfloat16 g_Bh[(size_t)NDIM * KDIM];
__device__ __align__(16) __nv_bfloat16 g_Bl[(size_t)NDIM * KDIM];
__device__ float g_zsq[MDIM];
__device__ float g_esq[NDIM];
__device__ unsigned long long g_best[MDIM];
__device__ float g_partials[MDIM];

// ------------------------------------------------------------ PTX helpers
__device__ __forceinline__ uint32_t smem_u32(const void* p) {
    uint32_t a;
    asm("{ .reg .u64 t; cvta.to.shared.u64 t, %1; cvt.u32.u64 %0, t; }"
        : "=r"(a) : "l"(p));
    return a;
}
__device__ __forceinline__ void cp16(uint32_t dst, const void* src) {
    asm volatile("cp.async.cg.shared.global [%0], [%1], 16;"
                 :: "r"(dst), "l"(src) : "memory");
}
__device__ __forceinline__ void ldsm4(uint32_t* r, uint32_t addr) {
    asm volatile("ldmatrix.sync.aligned.m8n8.x4.shared.b16 {%0,%1,%2,%3}, [%4];"
                 : "=r"(r[0]), "=r"(r[1]), "=r"(r[2]), "=r"(r[3]) : "r"(addr));
}
__device__ __forceinline__ void mma16816(float* c, const uint32_t* a,
                                         uint32_t b0, uint32_t b1) {
    asm volatile(
        "mma.sync.aligned.m16n8k16.row.col.f32.bf16.bf16.f32 "
        "{%0,%1,%2,%3}, {%4,%5,%6,%7}, {%8,%9}, {%0,%1,%2,%3};"
        : "+f"(c[0]), "+f"(c[1]), "+f"(c[2]), "+f"(c[3])
        : "r"(a[0]), "r"(a[1]), "r"(a[2]), "r"(a[3]), "r"(b0), "r"(b1));
}
// 64-byte-row swizzle (rows of 64B): XOR bits[5:4] with bits[8:7]
__device__ __forceinline__ uint32_t swz64(uint32_t off) {
    return off ^ ((off >> 3) & 0x30);
}
__device__ __forceinline__ uint32_t packbf2(__nv_bfloat16 a, __nv_bfloat16 b) {
    __nv_bfloat162 t; t.x = a; t.y = b;
    return *(uint32_t*)&t;
}

// ------------------------------------------------------------ split kernels
__global__ void splitA_kernel(const float* __restrict__ z)
{
    int i = blockIdx.x * 256 + threadIdx.x;     // over MDIM*128
    int m = i >> 7, kc = (i & 127) << 2;
    float4 v = *(const float4*)(z + (size_t)m * KDIM + kc);
    __nv_bfloat16 h0 = __float2bfloat16(v.x), h1 = __float2bfloat16(v.y);
    __nv_bfloat16 h2 = __float2bfloat16(v.z), h3 = __float2bfloat16(v.w);
    __nv_bfloat16 l0 = __float2bfloat16(v.x - __bfloat162float(h0));
    __nv_bfloat16 l1 = __float2bfloat16(v.y - __bfloat162float(h1));
    __nv_bfloat16 l2 = __float2bfloat16(v.z - __bfloat162float(h2));
    __nv_bfloat16 l3 = __float2bfloat16(v.w - __bfloat162float(h3));
    uint2 H; H.x = packbf2(h0, h1); H.y = packbf2(h2, h3);
    uint2 L; L.x = packbf2(l0, l1); L.y = packbf2(l2, l3);
    *(uint2*)(g_Ah + (size_t)m * KDIM + kc) = H;
    *(uint2*)(g_Al + (size_t)m * KDIM + kc) = L;
}
__global__ void splitB_kernel(const float* __restrict__ cb)
{
    int i = blockIdx.x * 256 + threadIdx.x;     // over NDIM*128
    int n = i >> 7, kc = (i & 127) << 2;
    float4 v = *(const float4*)(cb + (size_t)n * KDIM + kc);
    __nv_bfloat16 h0 = __float2bfloat16(v.x), h1 = __float2bfloat16(v.y);
    __nv_bfloat16 h2 = __float2bfloat16(v.z), h3 = __float2bfloat16(v.w);
    __nv_bfloat16 l0 = __float2bfloat16(v.x - __bfloat162float(h0));
    __nv_bfloat16 l1 = __float2bfloat16(v.y - __bfloat162float(h1));
    __nv_bfloat16 l2 = __float2bfloat16(v.z - __bfloat162float(h2));
    __nv_bfloat16 l3 = __float2bfloat16(v.w - __bfloat162float(h3));
    uint2 H; H.x = packbf2(h0, h1); H.y = packbf2(h2, h3);
    uint2 L; L.x = packbf2(l0, l1); L.y = packbf2(l2, l3);
    *(uint2*)(g_Bh + (size_t)n * KDIM + kc) = H;
    *(uint2*)(g_Bl + (size_t)n * KDIM + kc) = L;
}

// ------------------------------------------------------------ row sumsq
__global__ void rowsq_kernel(const float* __restrict__ x, int K, int which)
{
    int row = blockIdx.x;
    const float* xr = x + (size_t)row * K;
    float s = 0.f;
    for (int c = threadIdx.x; c < K; c += 128) { float v = xr[c]; s += v * v; }
    #pragma unroll
    for (int o = 16; o; o >>= 1) s += __shfl_down_sync(0xffffffffu, s, o);
    __shared__ float ws[4];
    if ((threadIdx.x & 31) == 0) ws[threadIdx.x >> 5] = s;
    __syncthreads();
    if (threadIdx.x == 0) {
        float t = ws[0] + ws[1] + ws[2] + ws[3];
        if (which) g_esq[row] = t; else g_zsq[row] = t;
    }
}

__global__ void init_best_kernel(int M)
{
    int i = blockIdx.x * blockDim.x + threadIdx.x;
    if (i < M) g_best[i] = 0xFFFFFFFFFFFFFFFFull;
}

// ------------------------------------------------------------ HMMA GEMM+argmin
__global__ __launch_bounds__(512, 1)
void gemm_hmma_kernel()
{
    extern __shared__ char smem[];
    __shared__ unsigned long long sred[BM];
    __shared__ float s_esq[BN];
    const uint32_t smb = smem_u32(smem);
    const int tid = threadIdx.x;
    const int lane = tid & 31, warp = tid >> 5;
    const int m0 = blockIdx.y * BM;
    const int n0 = blockIdx.x * BN;

    // per-thread cp.async chunk descriptors: each 16KB region = 2 chunks/thread
    // chunk q: row = q>>2 (64B rows, 4 x 16B chunks), c = q&3
    uint32_t swo[2];
    const __nv_bfloat16 *sAh[2], *sAl[2], *sBh[2], *sBl[2];
    #pragma unroll
    for (int r = 0; r < 2; r++) {
        int q = tid + r * 512, row = q >> 2, c = q & 3;
        swo[r] = swz64(row * 64 + c * 16);
        sAh[r] = g_Ah + (size_t)(m0 + row) * KDIM + c * 8;
        sAl[r] = g_Al + (size_t)(m0 + row) * KDIM + c * 8;
        sBh[r] = g_Bh + (size_t)(n0 + row) * KDIM + c * 8;
        sBl[r] = g_Bl + (size_t)(n0 + row) * KDIM + c * 8;
    }

    // prologue: stages 0..STAGES-2
    #pragma unroll
    for (int s = 0; s < STAGES - 1; s++) {
        uint32_t bo = (uint32_t)s * STG;
        int k0 = s * BK;
        #pragma unroll
        for (int r = 0; r < 2; r++) {
            cp16(smb + bo + swo[r],        sAh[r] + k0);
            cp16(smb + bo + R_AL + swo[r], sAl[r] + k0);
            cp16(smb + bo + R_BH + swo[r], sBh[r] + k0);
            cp16(smb + bo + R_BL + swo[r], sBl[r] + k0);
        }
        asm volatile("cp.async.commit_group;" ::: "memory");
    }

    if (tid < BM) sred[tid] = 0xFFFFFFFFFFFFFFFFull;
    if (tid < BN) s_esq[tid] = g_esq[n0 + tid];

    float acc[4][8][4];
    #pragma unroll
    for (int i = 0; i < 4; i++)
        #pragma unroll
        for (int j = 0; j < 8; j++)
            #pragma unroll
            for (int q = 0; q < 4; q++) acc[i][j][q] = 0.f;

    const int wm = (warp >> 2) * 64;      // warp row base (4 warp-rows in M)
    const int wn = (warp & 3) * 64;       // warp col base (4 warp-cols in N)
    const uint32_t a_row = wm + (lane & 15);
    const uint32_t b_row = wn + (lane & 15);
    const uint32_t kchunk = (lane >> 4);  // 0/1: which 16B chunk of the k16 slice

    for (int kt = 0; kt < NKT; kt++) {
        asm volatile("cp.async.wait_group %0;" :: "n"(STAGES - 2));
        __syncthreads();

        // prefetch stage kt+STAGES-1 (overwrites buffer compute just released)
        int pf = kt + STAGES - 1;
        if (pf < NKT) {
            uint32_t bo = (uint32_t)(pf % STAGES) * STG;
            int k0 = pf * BK;
            #pragma unroll
            for (int r = 0; r < 2; r++) {
                cp16(smb + bo + swo[r],        sAh[r] + k0);
                cp16(smb + bo + R_AL + swo[r], sAl[r] + k0);
                cp16(smb + bo + R_BH + swo[r], sBh[r] + k0);
                cp16(smb + bo + R_BL + swo[r], sBl[r] + k0);
            }
        }
        asm volatile("cp.async.commit_group;" ::: "memory");

        const uint32_t sA = smb + (uint32_t)(kt % STAGES) * STG;
        #pragma unroll
        for (int kk = 0; kk < 2; kk++) {
            const uint32_t kof = (kk * 2 + kchunk) * 16;
            uint32_t aH[4][4], aL[4][4], b[4][4];
            #pragma unroll
            for (int i = 0; i < 4; i++)
                ldsm4(aH[i], sA + swz64((a_row + i * 16) * 64 + kof));
            #pragma unroll
            for (int i = 0; i < 4; i++)
                ldsm4(aL[i], sA + R_AL + swz64((a_row + i * 16) * 64 + kof));
            #pragma unroll
            for (int p = 0; p < 4; p++)
                ldsm4(b[p], sA + R_BH + swz64((b_row + p * 16) * 64 + kof));
            #pragma unroll
            for (int i = 0; i < 4; i++)
                #pragma unroll
                for (int j = 0; j < 8; j++) {
                    int p = j >> 1, h = j & 1;
                    mma16816(acc[i][j], aH[i], b[p][h], b[p][h + 2]);
                }
            #pragma unroll
            for (int i = 0; i < 4; i++)
                #pragma unroll
                for (int j = 0; j < 8; j++) {
                    int p = j >> 1, h = j & 1;
                    mma16816(acc[i][j], aL[i], b[p][h], b[p][h + 2]);
                }
            #pragma unroll
            for (int p = 0; p < 4; p++)
                ldsm4(b[p], sA + R_BL + swz64((b_row + p * 16) * 64 + kof));
            #pragma unroll
            for (int i = 0; i < 4; i++)
                #pragma unroll
                for (int j = 0; j < 8; j++) {
                    int p = j >> 1, h = j & 1;
                    mma16816(acc[i][j], aH[i], b[p][h], b[p][h + 2]);
                }
        }
    }

    // ---- epilogue: dist = (zsq+esq) - 2*acc, fused per-row argmin
    const int r0 = lane >> 2;
    #pragma unroll
    for (int i = 0; i < 4; i++) {
        int rowa = wm + i * 16 + r0;
        float zs0 = g_zsq[m0 + rowa];
        float zs1 = g_zsq[m0 + rowa + 8];
        unsigned long long bk0 = 0xFFFFFFFFFFFFFFFFull;
        unsigned long long bk1 = 0xFFFFFFFFFFFFFFFFull;
        #pragma unroll
        for (int j = 0; j < 8; j++) {
            int ncol = wn + j * 8 + 2 * (lane & 3);
            float e0 = s_esq[ncol], e1 = s_esq[ncol + 1];
            unsigned gn0 = (unsigned)(n0 + ncol), gn1 = gn0 + 1;
            float d;
            unsigned u;
            unsigned long long k;
            d = (zs0 + e0) - 2.0f * acc[i][j][0];
            u = __float_as_uint(d); u = (u & 0x80000000u) ? ~u : (u | 0x80000000u);
            k = ((unsigned long long)u << 32) | gn0; if (k < bk0) bk0 = k;
            d = (zs0 + e1) - 2.0f * acc[i][j][1];
            u = __float_as_uint(d); u = (u & 0x80000000u) ? ~u : (u | 0x80000000u);
            k = ((unsigned long long)u << 32) | gn1; if (k < bk0) bk0 = k;
            d = (zs1 + e0) - 2.0f * acc[i][j][2];
            u = __float_as_uint(d); u = (u & 0x80000000u) ? ~u : (u | 0x80000000u);
            k = ((unsigned long long)u << 32) | gn0; if (k < bk1) bk1 = k;
            d = (zs1 + e1) - 2.0f * acc[i][j][3];
            u = __float_as_uint(d); u = (u & 0x80000000u) ? ~u : (u | 0x80000000u);
            k = ((unsigned long long)u << 32) | gn1; if (k < bk1) bk1 = k;
        }
        // reduce across the 4 lanes sharing this row
        #pragma unroll
        for (int o = 1; o <= 2; o <<= 1) {
            unsigned long long t0 = __shfl_xor_sync(0xffffffffu, bk0, o);
            unsigned long long t1 = __shfl_xor_sync(0xffffffffu, bk1, o);
            if (t0 < bk0) bk0 = t0;
            if (t1 < bk1) bk1 = t1;
        }
        if ((lane & 3) == 0) {
            atomicMin(&sred[rowa], bk0);
            atomicMin(&sred[rowa + 8], bk1);
        }
    }
    __syncthreads();
    if (tid < BM) atomicMin(&g_best[m0 + tid], sred[tid]);
}

// ------------------------------------------------------------ gather + loss
__global__ void gather_loss_kernel(const float* __restrict__ z,
                                   const float* __restrict__ cb,
                                   float* __restrict__ out_q,
                                   float* __restrict__ out_idx)
{
    int m = blockIdx.x;
    unsigned int idx = (unsigned int)(g_best[m] & 0xFFFFFFFFu);
    const float4* zr = (const float4*)(z + (size_t)m * KDIM);
    const float4* cr = (const float4*)(cb + (size_t)idx * KDIM);
    float4* qr = (float4*)(out_q + (size_t)m * KDIM);
    float4 ze = zr[threadIdx.x];
    float4 cq = cr[threadIdx.x];
    float d0 = cq.x - ze.x, d1 = cq.y - ze.y, d2 = cq.z - ze.z, d3 = cq.w - ze.w;
    float4 o;
    o.x = ze.x + d0; o.y = ze.y + d1; o.z = ze.z + d2; o.w = ze.w + d3;
    qr[threadIdx.x] = o;
    float s = d0 * d0 + d1 * d1 + d2 * d2 + d3 * d3;
    #pragma unroll
    for (int off = 16; off; off >>= 1) s += __shfl_down_sync(0xffffffffu, s, off);
    __shared__ float ws[4];
    if ((threadIdx.x & 31) == 0) ws[threadIdx.x >> 5] = s;
    __syncthreads();
    if (threadIdx.x == 0) {
        g_partials[m] = ws[0] + ws[1] + ws[2] + ws[3];
        out_idx[m] = (float)idx;
    }
}

__global__ void loss_kernel(float* __restrict__ out_loss, int M, int K)
{
    __shared__ float sm[1024];
    float s = 0.f;
    for (int i = threadIdx.x; i < M; i += 1024) s += g_partials[i];
    sm[threadIdx.x] = s;
    __syncthreads();
    for (int o = 512; o; o >>= 1) {
        if (threadIdx.x < o) sm[threadIdx.x] += sm[threadIdx.x + o];
        __syncthreads();
    }
    if (threadIdx.x == 0) {
        float mean = sm[0] / ((float)M * (float)K);
        out_loss[0] = (mean + 0.25f * mean) / (float)K;
    }
}

// ------------------------------------------------------------ launch
extern "C" void kernel_launch(void* const* d_in, const int* in_sizes, int n_in,
                              void* d_out, int out_size)
{
    const float* z  = (const float*)d_in[0];
    const float* cb = (const float*)d_in[1];
    const int M = in_sizes[0] / KDIM;   // 32768
    const int N = in_sizes[1] / KDIM;   // 8192

    float* out      = (float*)d_out;
    float* out_q    = out;
    float* out_idx  = out + (size_t)M * KDIM;
    float* out_loss = out_idx + M;

    static int attr_done = 0;
    if (!attr_done) {
        cudaFuncSetAttribute(gemm_hmma_kernel,
                             cudaFuncAttributeMaxDynamicSharedMemorySize,
                             SMEM_DYN);
        attr_done = 1;
    }

    splitA_kernel<<<M * 128 / 256, 256>>>(z);
    splitB_kernel<<<N * 128 / 256, 256>>>(cb);
    rowsq_kernel<<<M, 128>>>(z, KDIM, 0);
    rowsq_kernel<<<N, 128>>>(cb, KDIM, 1);
    init_best_kernel<<<(M + 255) / 256, 256>>>(M);

    dim3 grid(N / BN, M / BM);
    gemm_hmma_kernel<<<grid, 512, SMEM_DYN>>>();

    gather_loss_kernel<<<M, 128>>>(z, cb, out_q, out_idx);
    loss_kernel<<<1, 1024>>>(out_loss, M, KDIM);
}

// round 9
// speedup vs baseline: 2.6555x; 2.6555x over previous
#include <cuda_runtime.h>
#include <cuda_bf16.h>
#include <stdint.h>

// ----------------------------------------------------------------------------
// VQExpert via mma.sync bf16 (base ISA -> compiles for compute_103).
// bf16x3 split with shared-operand tiles: per k-tile load Ah,Al,Bh,Bl once,
// accumulate dot = Ah*Bh + Al*Bh + Ah*Bl (fp32 accum; AlBl dropped ~2e-6).
// dist = (zsq + esq) - 2*dot, fused per-row argmin, then gather + loss.
// R9: CTA 128x256, 256 threads, warp tile 64x64 (ratio 6 MMA/LDSM),
//     255-reg budget (occ 1) -- no spill, unlike R8's 512-thread variant.
// ----------------------------------------------------------------------------

#define KDIM 512
#define MDIM 32768
#define NDIM 8192
#define BM 128
#define BN 256
#define BK 32
#define STAGES 3
#define NKT (KDIM / BK)        // 16
// stage regions: Ah 8K | Al 8K | Bh 16K | Bl 16K ; stage = 48KB
#define R_AL 8192
#define R_BH 16384
#define R_BL 32768
#define STG  49152
#define SMEM_DYN (STAGES * STG)   // 147456

__device__ __align__(16) __nv_bfloat16 g_Ah[(size_t)MDIM * KDIM];
__device__ __align__(16) __nv_bfloat16 g_Al[(size_t)MDIM * KDIM];
__device__ __align__(16) __nv_bfloat16 g_Bh[(size_t)NDIM * KDIM];
__device__ __align__(16) __nv_bfloat16 g_Bl[(size_t)NDIM * KDIM];
__device__ float g_zsq[MDIM];
__device__ float g_esq[NDIM];
__device__ unsigned long long g_best[MDIM];
__device__ float g_partials[MDIM];

// ------------------------------------------------------------ PTX helpers
__device__ __forceinline__ uint32_t smem_u32(const void* p) {
    uint32_t a;
    asm("{ .reg .u64 t; cvta.to.shared.u64 t, %1; cvt.u32.u64 %0, t; }"
        : "=r"(a) : "l"(p));
    return a;
}
__device__ __forceinline__ void cp16(uint32_t dst, const void* src) {
    asm volatile("cp.async.cg.shared.global [%0], [%1], 16;"
                 :: "r"(dst), "l"(src) : "memory");
}
__device__ __forceinline__ void ldsm4(uint32_t* r, uint32_t addr) {
    asm volatile("ldmatrix.sync.aligned.m8n8.x4.shared.b16 {%0,%1,%2,%3}, [%4];"
                 : "=r"(r[0]), "=r"(r[1]), "=r"(r[2]), "=r"(r[3]) : "r"(addr));
}
__device__ __forceinline__ void mma16816(float* c, const uint32_t* a,
                                         uint32_t b0, uint32_t b1) {
    asm volatile(
        "mma.sync.aligned.m16n8k16.row.col.f32.bf16.bf16.f32 "
        "{%0,%1,%2,%3}, {%4,%5,%6,%7}, {%8,%9}, {%0,%1,%2,%3};"
        : "+f"(c[0]), "+f"(c[1]), "+f"(c[2]), "+f"(c[3])
        : "r"(a[0]), "r"(a[1]), "r"(a[2]), "r"(a[3]), "r"(b0), "r"(b1));
}
// 64-byte-row swizzle (rows of 64B): XOR bits[5:4] with bits[8:7]
__device__ __forceinline__ uint32_t swz64(uint32_t off) {
    return off ^ ((off >> 3) & 0x30);
}
__device__ __forceinline__ uint32_t packbf2(__nv_bfloat16 a, __nv_bfloat16 b) {
    __nv_bfloat162 t; t.x = a; t.y = b;
    return *(uint32_t*)&t;
}

// ------------------------------------------------------------ split kernels
__global__ void splitA_kernel(const float* __restrict__ z)
{
    int i = blockIdx.x * 256 + threadIdx.x;     // over MDIM*128
    int m = i >> 7, kc = (i & 127) << 2;
    float4 v = *(const float4*)(z + (size_t)m * KDIM + kc);
    __nv_bfloat16 h0 = __float2bfloat16(v.x), h1 = __float2bfloat16(v.y);
    __nv_bfloat16 h2 = __float2bfloat16(v.z), h3 = __float2bfloat16(v.w);
    __nv_bfloat16 l0 = __float2bfloat16(v.x - __bfloat162float(h0));
    __nv_bfloat16 l1 = __float2bfloat16(v.y - __bfloat162float(h1));
    __nv_bfloat16 l2 = __float2bfloat16(v.z - __bfloat162float(h2));
    __nv_bfloat16 l3 = __float2bfloat16(v.w - __bfloat162float(h3));
    uint2 H; H.x = packbf2(h0, h1); H.y = packbf2(h2, h3);
    uint2 L; L.x = packbf2(l0, l1); L.y = packbf2(l2, l3);
    *(uint2*)(g_Ah + (size_t)m * KDIM + kc) = H;
    *(uint2*)(g_Al + (size_t)m * KDIM + kc) = L;
}
__global__ void splitB_kernel(const float* __restrict__ cb)
{
    int i = blockIdx.x * 256 + threadIdx.x;     // over NDIM*128
    int n = i >> 7, kc = (i & 127) << 2;
    float4 v = *(const float4*)(cb + (size_t)n * KDIM + kc);
    __nv_bfloat16 h0 = __float2bfloat16(v.x), h1 = __float2bfloat16(v.y);
    __nv_bfloat16 h2 = __float2bfloat16(v.z), h3 = __float2bfloat16(v.w);
    __nv_bfloat16 l0 = __float2bfloat16(v.x - __bfloat162float(h0));
    __nv_bfloat16 l1 = __float2bfloat16(v.y - __bfloat162float(h1));
    __nv_bfloat16 l2 = __float2bfloat16(v.z - __bfloat162float(h2));
    __nv_bfloat16 l3 = __float2bfloat16(v.w - __bfloat162float(h3));
    uint2 H; H.x = packbf2(h0, h1); H.y = packbf2(h2, h3);
    uint2 L; L.x = packbf2(l0, l1); L.y = packbf2(l2, l3);
    *(uint2*)(g_Bh + (size_t)n * KDIM + kc) = H;
    *(uint2*)(g_Bl + (size_t)n * KDIM + kc) = L;
}

// ------------------------------------------------------------ row sumsq
__global__ void rowsq_kernel(const float* __restrict__ x, int K, int which)
{
    int row = blockIdx.x;
    const float* xr = x + (size_t)row * K;
    float s = 0.f;
    for (int c = threadIdx.x; c < K; c += 128) { float v = xr[c]; s += v * v; }
    #pragma unroll
    for (int o = 16; o; o >>= 1) s += __shfl_down_sync(0xffffffffu, s, o);
    __shared__ float ws[4];
    if ((threadIdx.x & 31) == 0) ws[threadIdx.x >> 5] = s;
    __syncthreads();
    if (threadIdx.x == 0) {
        float t = ws[0] + ws[1] + ws[2] + ws[3];
        if (which) g_esq[row] = t; else g_zsq[row] = t;
    }
}

__global__ void init_best_kernel(int M)
{
    int i = blockIdx.x * blockDim.x + threadIdx.x;
    if (i < M) g_best[i] = 0xFFFFFFFFFFFFFFFFull;
}

// ------------------------------------------------------------ HMMA GEMM+argmin
__global__ __launch_bounds__(256, 1)
void gemm_hmma_kernel()
{
    extern __shared__ char smem[];
    __shared__ unsigned long long sred[BM];
    __shared__ float s_esq[BN];
    const uint32_t smb = smem_u32(smem);
    const int tid = threadIdx.x;
    const int lane = tid & 31, warp = tid >> 5;
    const int m0 = blockIdx.y * BM;
    const int n0 = blockIdx.x * BN;

    // cp.async descriptors.
    // A regions (8KB = 512 x 16B chunks): 2 chunks/thread.
    // B regions (16KB = 1024 x 16B chunks): 4 chunks/thread.
    uint32_t swoA[2], swoB[4];
    const __nv_bfloat16 *pAh[2], *pAl[2], *pBh[4], *pBl[4];
    #pragma unroll
    for (int r = 0; r < 2; r++) {
        int q = tid + r * 256, row = q >> 2, c = q & 3;
        swoA[r] = swz64(row * 64 + c * 16);
        pAh[r] = g_Ah + (size_t)(m0 + row) * KDIM + c * 8;
        pAl[r] = g_Al + (size_t)(m0 + row) * KDIM + c * 8;
    }
    #pragma unroll
    for (int r = 0; r < 4; r++) {
        int q = tid + r * 256, row = q >> 2, c = q & 3;
        swoB[r] = swz64(row * 64 + c * 16);
        pBh[r] = g_Bh + (size_t)(n0 + row) * KDIM + c * 8;
        pBl[r] = g_Bl + (size_t)(n0 + row) * KDIM + c * 8;
    }

    // prologue: stages 0..STAGES-2
    #pragma unroll
    for (int s = 0; s < STAGES - 1; s++) {
        uint32_t bo = (uint32_t)s * STG;
        int k0 = s * BK;
        #pragma unroll
        for (int r = 0; r < 2; r++) {
            cp16(smb + bo + swoA[r],        pAh[r] + k0);
            cp16(smb + bo + R_AL + swoA[r], pAl[r] + k0);
        }
        #pragma unroll
        for (int r = 0; r < 4; r++) {
            cp16(smb + bo + R_BH + swoB[r], pBh[r] + k0);
            cp16(smb + bo + R_BL + swoB[r], pBl[r] + k0);
        }
        asm volatile("cp.async.commit_group;" ::: "memory");
    }

    if (tid < BM) sred[tid] = 0xFFFFFFFFFFFFFFFFull;
    s_esq[tid] = g_esq[n0 + tid];   // 256 threads, BN=256

    float acc[4][8][4];
    #pragma unroll
    for (int i = 0; i < 4; i++)
        #pragma unroll
        for (int j = 0; j < 8; j++)
            #pragma unroll
            for (int q = 0; q < 4; q++) acc[i][j][q] = 0.f;

    const int wm = (warp >> 2) * 64;      // 2 warp-rows in M (128)
    const int wn = (warp & 3) * 64;       // 4 warp-cols in N (256)
    const uint32_t a_row = wm + (lane & 15);
    const uint32_t b_row = wn + (lane & 15);
    const uint32_t kchunk = (lane >> 4);  // 0/1: which 16B chunk of the k16 slice

    for (int kt = 0; kt < NKT; kt++) {
        asm volatile("cp.async.wait_group %0;" :: "n"(STAGES - 2));
        __syncthreads();

        // prefetch stage kt+STAGES-1 (overwrites buffer compute just released)
        int pf = kt + STAGES - 1;
        if (pf < NKT) {
            uint32_t bo = (uint32_t)(pf % STAGES) * STG;
            int k0 = pf * BK;
            #pragma unroll
            for (int r = 0; r < 2; r++) {
                cp16(smb + bo + swoA[r],        pAh[r] + k0);
                cp16(smb + bo + R_AL + swoA[r], pAl[r] + k0);
            }
            #pragma unroll
            for (int r = 0; r < 4; r++) {
                cp16(smb + bo + R_BH + swoB[r], pBh[r] + k0);
                cp16(smb + bo + R_BL + swoB[r], pBl[r] + k0);
            }
        }
        asm volatile("cp.async.commit_group;" ::: "memory");

        const uint32_t sA = smb + (uint32_t)(kt % STAGES) * STG;
        #pragma unroll
        for (int kk = 0; kk < 2; kk++) {
            const uint32_t kof = (kk * 2 + kchunk) * 16;
            uint32_t aH[4][4], aL[4][4], b[4][4];
            #pragma unroll
            for (int i = 0; i < 4; i++)
                ldsm4(aH[i], sA + swz64((a_row + i * 16) * 64 + kof));
            #pragma unroll
            for (int i = 0; i < 4; i++)
                ldsm4(aL[i], sA + R_AL + swz64((a_row + i * 16) * 64 + kof));
            #pragma unroll
            for (int p = 0; p < 4; p++)
                ldsm4(b[p], sA + R_BH + swz64((b_row + p * 16) * 64 + kof));
            #pragma unroll
            for (int i = 0; i < 4; i++)
                #pragma unroll
                for (int j = 0; j < 8; j++) {
                    int p = j >> 1, h = j & 1;
                    mma16816(acc[i][j], aH[i], b[p][h], b[p][h + 2]);
                }
            #pragma unroll
            for (int i = 0; i < 4; i++)
                #pragma unroll
                for (int j = 0; j < 8; j++) {
                    int p = j >> 1, h = j & 1;
                    mma16816(acc[i][j], aL[i], b[p][h], b[p][h + 2]);
                }
            #pragma unroll
            for (int p = 0; p < 4; p++)
                ldsm4(b[p], sA + R_BL + swz64((b_row + p * 16) * 64 + kof));
            #pragma unroll
            for (int i = 0; i < 4; i++)
                #pragma unroll
                for (int j = 0; j < 8; j++) {
                    int p = j >> 1, h = j & 1;
                    mma16816(acc[i][j], aH[i], b[p][h], b[p][h + 2]);
                }
        }
    }

    // ---- epilogue: dist = (zsq+esq) - 2*acc, fused per-row argmin
    const int r0 = lane >> 2;
    #pragma unroll
    for (int i = 0; i < 4; i++) {
        int rowa = wm + i * 16 + r0;
        float zs0 = g_zsq[m0 + rowa];
        float zs1 = g_zsq[m0 + rowa + 8];
        unsigned long long bk0 = 0xFFFFFFFFFFFFFFFFull;
        unsigned long long bk1 = 0xFFFFFFFFFFFFFFFFull;
        #pragma unroll
        for (int j = 0; j < 8; j++) {
            int ncol = wn + j * 8 + 2 * (lane & 3);
            float e0 = s_esq[ncol], e1 = s_esq[ncol + 1];
            unsigned gn0 = (unsigned)(n0 + ncol), gn1 = gn0 + 1;
            float d;
            unsigned u;
            unsigned long long k;
            d = (zs0 + e0) - 2.0f * acc[i][j][0];
            u = __float_as_uint(d); u = (u & 0x80000000u) ? ~u : (u | 0x80000000u);
            k = ((unsigned long long)u << 32) | gn0; if (k < bk0) bk0 = k;
            d = (zs0 + e1) - 2.0f * acc[i][j][1];
            u = __float_as_uint(d); u = (u & 0x80000000u) ? ~u : (u | 0x80000000u);
            k = ((unsigned long long)u << 32) | gn1; if (k < bk0) bk0 = k;
            d = (zs1 + e0) - 2.0f * acc[i][j][2];
            u = __float_as_uint(d); u = (u & 0x80000000u) ? ~u : (u | 0x80000000u);
            k = ((unsigned long long)u << 32) | gn0; if (k < bk1) bk1 = k;
            d = (zs1 + e1) - 2.0f * acc[i][j][3];
            u = __float_as_uint(d); u = (u & 0x80000000u) ? ~u : (u | 0x80000000u);
            k = ((unsigned long long)u << 32) | gn1; if (k < bk1) bk1 = k;
        }
        // reduce across the 4 lanes sharing this row
        #pragma unroll
        for (int o = 1; o <= 2; o <<= 1) {
            unsigned long long t0 = __shfl_xor_sync(0xffffffffu, bk0, o);
            unsigned long long t1 = __shfl_xor_sync(0xffffffffu, bk1, o);
            if (t0 < bk0) bk0 = t0;
            if (t1 < bk1) bk1 = t1;
        }
        if ((lane & 3) == 0) {
            atomicMin(&sred[rowa], bk0);
            atomicMin(&sred[rowa + 8], bk1);
        }
    }
    __syncthreads();
    if (tid < BM) atomicMin(&g_best[m0 + tid], sred[tid]);
}

// ------------------------------------------------------------ gather + loss
__global__ void gather_loss_kernel(const float* __restrict__ z,
                                   const float* __restrict__ cb,
                                   float* __restrict__ out_q,
                                   float* __restrict__ out_idx)
{
    int m = blockIdx.x;
    unsigned int idx = (unsigned int)(g_best[m] & 0xFFFFFFFFu);
    const float4* zr = (const float4*)(z + (size_t)m * KDIM);
    const float4* cr = (const float4*)(cb + (size_t)idx * KDIM);
    float4* qr = (float4*)(out_q + (size_t)m * KDIM);
    float4 ze = zr[threadIdx.x];
    float4 cq = cr[threadIdx.x];
    float d0 = cq.x - ze.x, d1 = cq.y - ze.y, d2 = cq.z - ze.z, d3 = cq.w - ze.w;
    float4 o;
    o.x = ze.x + d0; o.y = ze.y + d1; o.z = ze.z + d2; o.w = ze.w + d3;
    qr[threadIdx.x] = o;
    float s = d0 * d0 + d1 * d1 + d2 * d2 + d3 * d3;
    #pragma unroll
    for (int off = 16; off; off >>= 1) s += __shfl_down_sync(0xffffffffu, s, off);
    __shared__ float ws[4];
    if ((threadIdx.x & 31) == 0) ws[threadIdx.x >> 5] = s;
    __syncthreads();
    if (threadIdx.x == 0) {
        g_partials[m] = ws[0] + ws[1] + ws[2] + ws[3];
        out_idx[m] = (float)idx;
    }
}

__global__ void loss_kernel(float* __restrict__ out_loss, int M, int K)
{
    __shared__ float sm[1024];
    float s = 0.f;
    for (int i = threadIdx.x; i < M; i += 1024) s += g_partials[i];
    sm[threadIdx.x] = s;
    __syncthreads();
    for (int o = 512; o; o >>= 1) {
        if (threadIdx.x < o) sm[threadIdx.x] += sm[threadIdx.x + o];
        __syncthreads();
    }
    if (threadIdx.x == 0) {
        float mean = sm[0] / ((float)M * (float)K);
        out_loss[0] = (mean + 0.25f * mean) / (float)K;
    }
}

// ------------------------------------------------------------ launch
extern "C" void kernel_launch(void* const* d_in, const int* in_sizes, int n_in,
                              void* d_out, int out_size)
{
    const float* z  = (const float*)d_in[0];
    const float* cb = (const float*)d_in[1];
    const int M = in_sizes[0] / KDIM;   // 32768
    const int N = in_sizes[1] / KDIM;   // 8192

    float* out      = (float*)d_out;
    float* out_q    = out;
    float* out_idx  = out + (size_t)M * KDIM;
    float* out_loss = out_idx + M;

    static int attr_done = 0;
    if (!attr_done) {
        cudaFuncSetAttribute(gemm_hmma_kernel,
                             cudaFuncAttributeMaxDynamicSharedMemorySize,
                             SMEM_DYN);
        attr_done = 1;
    }

    splitA_kernel<<<M * 128 / 256, 256>>>(z);
    splitB_kernel<<<N * 128 / 256, 256>>>(cb);
    rowsq_kernel<<<M, 128>>>(z, KDIM, 0);
    rowsq_kernel<<<N, 128>>>(cb, KDIM, 1);
    init_best_kernel<<<(M + 255) / 256, 256>>>(M);

    dim3 grid(N / BN, M / BM);
    gemm_hmma_kernel<<<grid, 256, SMEM_DYN>>>();

    gather_loss_kernel<<<M, 128>>>(z, cb, out_q, out_idx);
    loss_kernel<<<1, 1024>>>(out_loss, M, KDIM);
}

// round 10
// speedup vs baseline: 2.8934x; 1.0896x over previous
#include <cuda_runtime.h>
#include <cuda_bf16.h>
#include <stdint.h>

// ----------------------------------------------------------------------------
// VQExpert via mma.sync bf16 (base ISA -> compiles for compute_103).
// bf16x3 split with shared-operand tiles: per k-tile load Ah,Al,Bh,Bl once,
// accumulate dot = Ah*Bh + Al*Bh + Ah*Bl (fp32 accum; AlBl dropped ~2e-6).
// dist = (zsq + esq) - 2*dot, fused per-row argmin, then gather + loss.
// R10: R7 base (BK=32, 96KB, 2 CTAs/SM) + LDSM spread between MMA groups
//      + sumsq fused into split kernels.
// ----------------------------------------------------------------------------

#define KDIM 512
#define MDIM 32768
#define NDIM 8192
#define BM 128
#define BN 128
#define BK 32
#define STAGES 3
#define NKT (KDIM / BK)        // 16
// stage regions (each BM*BK*2 = 8KB): Ah | Al | Bh | Bl ; stage = 32KB
#define R_AL 8192
#define R_BH 16384
#define R_BL 24576
#define STG  32768
#define SMEM_DYN (STAGES * STG)   // 98304

__device__ __align__(16) __nv_bfloat16 g_Ah[(size_t)MDIM * KDIM];
__device__ __align__(16) __nv_bfloat16 g_Al[(size_t)MDIM * KDIM];
__device__ __align__(16) __nv_bfloat16 g_Bh[(size_t)NDIM * KDIM];
__device__ __align__(16) __nv_bfloat16 g_Bl[(size_t)NDIM * KDIM];
__device__ float g_zsq[MDIM];
__device__ float g_esq[NDIM];
__device__ unsigned long long g_best[MDIM];
__device__ float g_partials[MDIM];

// ------------------------------------------------------------ PTX helpers
__device__ __forceinline__ uint32_t smem_u32(const void* p) {
    uint32_t a;
    asm("{ .reg .u64 t; cvta.to.shared.u64 t, %1; cvt.u32.u64 %0, t; }"
        : "=r"(a) : "l"(p));
    return a;
}
__device__ __forceinline__ void cp16(uint32_t dst, const void* src) {
    asm volatile("cp.async.cg.shared.global [%0], [%1], 16;"
                 :: "r"(dst), "l"(src) : "memory");
}
__device__ __forceinline__ void ldsm4(uint32_t* r, uint32_t addr) {
    asm volatile("ldmatrix.sync.aligned.m8n8.x4.shared.b16 {%0,%1,%2,%3}, [%4];"
                 : "=r"(r[0]), "=r"(r[1]), "=r"(r[2]), "=r"(r[3]) : "r"(addr));
}
__device__ __forceinline__ void mma16816(float* c, const uint32_t* a,
                                         uint32_t b0, uint32_t b1) {
    asm volatile(
        "mma.sync.aligned.m16n8k16.row.col.f32.bf16.bf16.f32 "
        "{%0,%1,%2,%3}, {%4,%5,%6,%7}, {%8,%9}, {%0,%1,%2,%3};"
        : "+f"(c[0]), "+f"(c[1]), "+f"(c[2]), "+f"(c[3])
        : "r"(a[0]), "r"(a[1]), "r"(a[2]), "r"(a[3]), "r"(b0), "r"(b1));
}
// 64-byte-row swizzle (rows of 64B): XOR bits[5:4] with bits[8:7]
__device__ __forceinline__ uint32_t swz64(uint32_t off) {
    return off ^ ((off >> 3) & 0x30);
}
__device__ __forceinline__ uint32_t packbf2(__nv_bfloat16 a, __nv_bfloat16 b) {
    __nv_bfloat162 t; t.x = a; t.y = b;
    return *(uint32_t*)&t;
}

// ------------------------------------------------------------ split + sumsq
// 256 threads/block; tid 0..127 cover row 2b, 128..255 cover row 2b+1;
// thread handles 4 consecutive floats. Also reduces sum(x^2) per row.
__global__ void splitA_kernel(const float* __restrict__ z)
{
    int i = blockIdx.x * 256 + threadIdx.x;     // over MDIM*128
    int m = i >> 7, kc = (i & 127) << 2;
    float4 v = *(const float4*)(z + (size_t)m * KDIM + kc);
    __nv_bfloat16 h0 = __float2bfloat16(v.x), h1 = __float2bfloat16(v.y);
    __nv_bfloat16 h2 = __float2bfloat16(v.z), h3 = __float2bfloat16(v.w);
    __nv_bfloat16 l0 = __float2bfloat16(v.x - __bfloat162float(h0));
    __nv_bfloat16 l1 = __float2bfloat16(v.y - __bfloat162float(h1));
    __nv_bfloat16 l2 = __float2bfloat16(v.z - __bfloat162float(h2));
    __nv_bfloat16 l3 = __float2bfloat16(v.w - __bfloat162float(h3));
    uint2 H; H.x = packbf2(h0, h1); H.y = packbf2(h2, h3);
    uint2 L; L.x = packbf2(l0, l1); L.y = packbf2(l2, l3);
    *(uint2*)(g_Ah + (size_t)m * KDIM + kc) = H;
    *(uint2*)(g_Al + (size_t)m * KDIM + kc) = L;
    // sumsq
    float s = v.x * v.x + v.y * v.y + v.z * v.z + v.w * v.w;
    #pragma unroll
    for (int o = 16; o; o >>= 1) s += __shfl_down_sync(0xffffffffu, s, o);
    __shared__ float ws[8];
    int t = threadIdx.x;
    if ((t & 31) == 0) ws[t >> 5] = s;
    __syncthreads();
    if (t == 0)   g_zsq[m] = ws[0] + ws[1] + ws[2] + ws[3];
    if (t == 128) g_zsq[m] = ws[4] + ws[5] + ws[6] + ws[7];
}
__global__ void splitB_kernel(const float* __restrict__ cb)
{
    int i = blockIdx.x * 256 + threadIdx.x;     // over NDIM*128
    int n = i >> 7, kc = (i & 127) << 2;
    float4 v = *(const float4*)(cb + (size_t)n * KDIM + kc);
    __nv_bfloat16 h0 = __float2bfloat16(v.x), h1 = __float2bfloat16(v.y);
    __nv_bfloat16 h2 = __float2bfloat16(v.z), h3 = __float2bfloat16(v.w);
    __nv_bfloat16 l0 = __float2bfloat16(v.x - __bfloat162float(h0));
    __nv_bfloat16 l1 = __float2bfloat16(v.y - __bfloat162float(h1));
    __nv_bfloat16 l2 = __float2bfloat16(v.z - __bfloat162float(h2));
    __nv_bfloat16 l3 = __float2bfloat16(v.w - __bfloat162float(h3));
    uint2 H; H.x = packbf2(h0, h1); H.y = packbf2(h2, h3);
    uint2 L; L.x = packbf2(l0, l1); L.y = packbf2(l2, l3);
    *(uint2*)(g_Bh + (size_t)n * KDIM + kc) = H;
    *(uint2*)(g_Bl + (size_t)n * KDIM + kc) = L;
    float s = v.x * v.x + v.y * v.y + v.z * v.z + v.w * v.w;
    #pragma unroll
    for (int o = 16; o; o >>= 1) s += __shfl_down_sync(0xffffffffu, s, o);
    __shared__ float ws[8];
    int t = threadIdx.x;
    if ((t & 31) == 0) ws[t >> 5] = s;
    __syncthreads();
    if (t == 0)   g_esq[n] = ws[0] + ws[1] + ws[2] + ws[3];
    if (t == 128) g_esq[n] = ws[4] + ws[5] + ws[6] + ws[7];
}

__global__ void init_best_kernel(int M)
{
    int i = blockIdx.x * blockDim.x + threadIdx.x;
    if (i < M) g_best[i] = 0xFFFFFFFFFFFFFFFFull;
}

// ------------------------------------------------------------ HMMA GEMM+argmin
__global__ __launch_bounds__(256, 2)
void gemm_hmma_kernel()
{
    extern __shared__ char smem[];
    __shared__ unsigned long long sred[BM];
    __shared__ float s_esq[BN];
    const uint32_t smb = smem_u32(smem);
    const int tid = threadIdx.x;
    const int lane = tid & 31, warp = tid >> 5;
    const int m0 = blockIdx.y * BM;
    const int n0 = blockIdx.x * BN;

    // per-thread cp.async chunk descriptors: each 8KB region = 2 chunks/thread
    uint32_t swo[2];
    const __nv_bfloat16 *sAh[2], *sAl[2], *sBh[2], *sBl[2];
    #pragma unroll
    for (int r = 0; r < 2; r++) {
        int q = tid + r * 256, row = q >> 2, c = q & 3;
        swo[r] = swz64(row * 64 + c * 16);
        sAh[r] = g_Ah + (size_t)(m0 + row) * KDIM + c * 8;
        sAl[r] = g_Al + (size_t)(m0 + row) * KDIM + c * 8;
        sBh[r] = g_Bh + (size_t)(n0 + row) * KDIM + c * 8;
        sBl[r] = g_Bl + (size_t)(n0 + row) * KDIM + c * 8;
    }

    // prologue: stages 0..STAGES-2
    #pragma unroll
    for (int s = 0; s < STAGES - 1; s++) {
        uint32_t bo = (uint32_t)s * STG;
        int k0 = s * BK;
        #pragma unroll
        for (int r = 0; r < 2; r++) {
            cp16(smb + bo + swo[r],        sAh[r] + k0);
            cp16(smb + bo + R_AL + swo[r], sAl[r] + k0);
            cp16(smb + bo + R_BH + swo[r], sBh[r] + k0);
            cp16(smb + bo + R_BL + swo[r], sBl[r] + k0);
        }
        asm volatile("cp.async.commit_group;" ::: "memory");
    }

    if (tid < BM) sred[tid] = 0xFFFFFFFFFFFFFFFFull;
    if (tid < BN) s_esq[tid] = g_esq[n0 + tid];

    float acc[4][4][4];
    #pragma unroll
    for (int i = 0; i < 4; i++)
        #pragma unroll
        for (int j = 0; j < 4; j++)
            #pragma unroll
            for (int q = 0; q < 4; q++) acc[i][j][q] = 0.f;

    const int wm = (warp & 1) * 64;       // warp row base (2 warps in M)
    const int wn = (warp >> 1) * 32;      // warp col base (4 warps in N)
    const uint32_t a_row = wm + (lane & 15);
    const uint32_t b_row = wn + (lane & 15);
    const uint32_t kchunk = (lane >> 4);  // 0/1: which 16B chunk of the k16 slice

    for (int kt = 0; kt < NKT; kt++) {
        asm volatile("cp.async.wait_group %0;" :: "n"(STAGES - 2));
        __syncthreads();

        // prefetch stage kt+STAGES-1 (overwrites buffer compute just released)
        int pf = kt + STAGES - 1;
        if (pf < NKT) {
            uint32_t bo = (uint32_t)(pf % STAGES) * STG;
            int k0 = pf * BK;
            #pragma unroll
            for (int r = 0; r < 2; r++) {
                cp16(smb + bo + swo[r],        sAh[r] + k0);
                cp16(smb + bo + R_AL + swo[r], sAl[r] + k0);
                cp16(smb + bo + R_BH + swo[r], sBh[r] + k0);
                cp16(smb + bo + R_BL + swo[r], sBl[r] + k0);
            }
        }
        asm volatile("cp.async.commit_group;" ::: "memory");

        const uint32_t sA = smb + (uint32_t)(kt % STAGES) * STG;
        #pragma unroll
        for (int kk = 0; kk < 2; kk++) {
            const uint32_t kof = (kk * 2 + kchunk) * 16;
            uint32_t aH[4][4], aL[4][4], b[2][4];
            // group 1: load aH + bh, run AhBh (its MMAs cover aL's latency)
            #pragma unroll
            for (int i = 0; i < 4; i++)
                ldsm4(aH[i], sA + swz64((a_row + i * 16) * 64 + kof));
            #pragma unroll
            for (int p = 0; p < 2; p++)
                ldsm4(b[p], sA + R_BH + swz64((b_row + p * 16) * 64 + kof));
            #pragma unroll
            for (int i = 0; i < 4; i++)
                #pragma unroll
                for (int j = 0; j < 4; j++) {
                    int p = j >> 1, h = j & 1;
                    mma16816(acc[i][j], aH[i], b[p][h], b[p][h + 2]);
                }
            // group 2: load aL, run AlBh (covers bl's latency)
            #pragma unroll
            for (int i = 0; i < 4; i++)
                ldsm4(aL[i], sA + R_AL + swz64((a_row + i * 16) * 64 + kof));
            #pragma unroll
            for (int i = 0; i < 4; i++)
                #pragma unroll
                for (int j = 0; j < 4; j++) {
                    int p = j >> 1, h = j & 1;
                    mma16816(acc[i][j], aL[i], b[p][h], b[p][h + 2]);
                }
            // group 3: load bl, run AhBl
            #pragma unroll
            for (int p = 0; p < 2; p++)
                ldsm4(b[p], sA + R_BL + swz64((b_row + p * 16) * 64 + kof));
            #pragma unroll
            for (int i = 0; i < 4; i++)
                #pragma unroll
                for (int j = 0; j < 4; j++) {
                    int p = j >> 1, h = j & 1;
                    mma16816(acc[i][j], aH[i], b[p][h], b[p][h + 2]);
                }
        }
    }

    // ---- epilogue: dist = (zsq+esq) - 2*acc, fused per-row argmin
    const int r0 = lane >> 2;
    #pragma unroll
    for (int i = 0; i < 4; i++) {
        int rowa = wm + i * 16 + r0;
        float zs0 = g_zsq[m0 + rowa];
        float zs1 = g_zsq[m0 + rowa + 8];
        unsigned long long bk0 = 0xFFFFFFFFFFFFFFFFull;
        unsigned long long bk1 = 0xFFFFFFFFFFFFFFFFull;
        #pragma unroll
        for (int j = 0; j < 4; j++) {
            int ncol = wn + j * 8 + 2 * (lane & 3);
            float e0 = s_esq[ncol], e1 = s_esq[ncol + 1];
            unsigned gn0 = (unsigned)(n0 + ncol), gn1 = gn0 + 1;
            float d;
            unsigned u;
            unsigned long long k;
            d = (zs0 + e0) - 2.0f * acc[i][j][0];
            u = __float_as_uint(d); u = (u & 0x80000000u) ? ~u : (u | 0x80000000u);
            k = ((unsigned long long)u << 32) | gn0; if (k < bk0) bk0 = k;
            d = (zs0 + e1) - 2.0f * acc[i][j][1];
            u = __float_as_uint(d); u = (u & 0x80000000u) ? ~u : (u | 0x80000000u);
            k = ((unsigned long long)u << 32) | gn1; if (k < bk0) bk0 = k;
            d = (zs1 + e0) - 2.0f * acc[i][j][2];
            u = __float_as_uint(d); u = (u & 0x80000000u) ? ~u : (u | 0x80000000u);
            k = ((unsigned long long)u << 32) | gn0; if (k < bk1) bk1 = k;
            d = (zs1 + e1) - 2.0f * acc[i][j][3];
            u = __float_as_uint(d); u = (u & 0x80000000u) ? ~u : (u | 0x80000000u);
            k = ((unsigned long long)u << 32) | gn1; if (k < bk1) bk1 = k;
        }
        // reduce across the 4 lanes sharing this row
        #pragma unroll
        for (int o = 1; o <= 2; o <<= 1) {
            unsigned long long t0 = __shfl_xor_sync(0xffffffffu, bk0, o);
            unsigned long long t1 = __shfl_xor_sync(0xffffffffu, bk1, o);
            if (t0 < bk0) bk0 = t0;
            if (t1 < bk1) bk1 = t1;
        }
        if ((lane & 3) == 0) {
            atomicMin(&sred[rowa], bk0);
            atomicMin(&sred[rowa + 8], bk1);
        }
    }
    __syncthreads();
    if (tid < BM) atomicMin(&g_best[m0 + tid], sred[tid]);
}

// ------------------------------------------------------------ gather + loss
__global__ void gather_loss_kernel(const float* __restrict__ z,
                                   const float* __restrict__ cb,
                                   float* __restrict__ out_q,
                                   float* __restrict__ out_idx)
{
    int m = blockIdx.x;
    unsigned int idx = (unsigned int)(g_best[m] & 0xFFFFFFFFu);
    const float4* zr = (const float4*)(z + (size_t)m * KDIM);
    const float4* cr = (const float4*)(cb + (size_t)idx * KDIM);
    float4* qr = (float4*)(out_q + (size_t)m * KDIM);
    float4 ze = zr[threadIdx.x];
    float4 cq = cr[threadIdx.x];
    float d0 = cq.x - ze.x, d1 = cq.y - ze.y, d2 = cq.z - ze.z, d3 = cq.w - ze.w;
    float4 o;
    o.x = ze.x + d0; o.y = ze.y + d1; o.z = ze.z + d2; o.w = ze.w + d3;
    qr[threadIdx.x] = o;
    float s = d0 * d0 + d1 * d1 + d2 * d2 + d3 * d3;
    #pragma unroll
    for (int off = 16; off; off >>= 1) s += __shfl_down_sync(0xffffffffu, s, off);
    __shared__ float ws[4];
    if ((threadIdx.x & 31) == 0) ws[threadIdx.x >> 5] = s;
    __syncthreads();
    if (threadIdx.x == 0) {
        g_partials[m] = ws[0] + ws[1] + ws[2] + ws[3];
        out_idx[m] = (float)idx;
    }
}

__global__ void loss_kernel(float* __restrict__ out_loss, int M, int K)
{
    __shared__ float sm[1024];
    float s = 0.f;
    for (int i = threadIdx.x; i < M; i += 1024) s += g_partials[i];
    sm[threadIdx.x] = s;
    __syncthreads();
    for (int o = 512; o; o >>= 1) {
        if (threadIdx.x < o) sm[threadIdx.x] += sm[threadIdx.x + o];
        __syncthreads();
    }
    if (threadIdx.x == 0) {
        float mean = sm[0] / ((float)M * (float)K);
        out_loss[0] = (mean + 0.25f * mean) / (float)K;
    }
}

// ------------------------------------------------------------ launch
extern "C" void kernel_launch(void* const* d_in, const int* in_sizes, int n_in,
                              void* d_out, int out_size)
{
    const float* z  = (const float*)d_in[0];
    const float* cb = (const float*)d_in[1];
    const int M = in_sizes[0] / KDIM;   // 32768
    const int N = in_sizes[1] / KDIM;   // 8192

    float* out      = (float*)d_out;
    float* out_q    = out;
    float* out_idx  = out + (size_t)M * KDIM;
    float* out_loss = out_idx + M;

    static int attr_done = 0;
    if (!attr_done) {
        cudaFuncSetAttribute(gemm_hmma_kernel,
                             cudaFuncAttributeMaxDynamicSharedMemorySize,
                             SMEM_DYN);
        attr_done = 1;
    }

    splitA_kernel<<<M * 128 / 256, 256>>>(z);
    splitB_kernel<<<N * 128 / 256, 256>>>(cb);
    init_best_kernel<<<(M + 255) / 256, 256>>>(M);

    dim3 grid(N / BN, M / BM);
    gemm_hmma_kernel<<<grid, 256, SMEM_DYN>>>();

    gather_loss_kernel<<<M, 128>>>(z, cb, out_q, out_idx);
    loss_kernel<<<1, 1024>>>(out_loss, M, KDIM);
}

// round 11
// speedup vs baseline: 3.2310x; 1.1167x over previous
#include <cuda_runtime.h>
#include <cuda_bf16.h>
#include <stdint.h>

// ----------------------------------------------------------------------------
// VQExpert, two-phase: (1) bf16 hi-only HMMA GEMM -> approximate distances,
// per-row per-16-code-group best keys; (2) refine: exact fp32 distance for
// all codes in groups within DELTA of the row's best approx distance
// (provable superset of the true argmin; DELTA ~ 35 sigma of approx error).
// dist form matches reference: (zsq + esq) - 2*dot, lowest-index tie-break.
// ----------------------------------------------------------------------------

#define KDIM 512
#define MDIM 32768
#define NDIM 8192
#define BM 128
#define BN 128
#define BK 32
#define STAGES 3
#define NKT (KDIM / BK)        // 16
#define NGRP (NDIM / 16)       // 512 groups of 16 codes
#define DELTA 0.10f
// stage regions: Ah 8KB | Bh 8KB ; stage = 16KB
#define R_BH 8192
#define STG  16384
#define SMEM_DYN (STAGES * STG)   // 49152

__device__ __align__(16) __nv_bfloat16 g_Ah[(size_t)MDIM * KDIM];
__device__ __align__(16) __nv_bfloat16 g_Bh[(size_t)NDIM * KDIM];
__device__ float g_zsq[MDIM];
__device__ float g_esq[NDIM];
__device__ unsigned long long g_gb[(size_t)MDIM * NGRP];  // per-row group keys
__device__ unsigned int g_bestidx[MDIM];
__device__ float g_partials[MDIM];

// ------------------------------------------------------------ PTX helpers
__device__ __forceinline__ uint32_t smem_u32(const void* p) {
    uint32_t a;
    asm("{ .reg .u64 t; cvta.to.shared.u64 t, %1; cvt.u32.u64 %0, t; }"
        : "=r"(a) : "l"(p));
    return a;
}
__device__ __forceinline__ void cp16(uint32_t dst, const void* src) {
    asm volatile("cp.async.cg.shared.global [%0], [%1], 16;"
                 :: "r"(dst), "l"(src) : "memory");
}
__device__ __forceinline__ void ldsm4(uint32_t* r, uint32_t addr) {
    asm volatile("ldmatrix.sync.aligned.m8n8.x4.shared.b16 {%0,%1,%2,%3}, [%4];"
                 : "=r"(r[0]), "=r"(r[1]), "=r"(r[2]), "=r"(r[3]) : "r"(addr));
}
__device__ __forceinline__ void mma16816(float* c, const uint32_t* a,
                                         uint32_t b0, uint32_t b1) {
    asm volatile(
        "mma.sync.aligned.m16n8k16.row.col.f32.bf16.bf16.f32 "
        "{%0,%1,%2,%3}, {%4,%5,%6,%7}, {%8,%9}, {%0,%1,%2,%3};"
        : "+f"(c[0]), "+f"(c[1]), "+f"(c[2]), "+f"(c[3])
        : "r"(a[0]), "r"(a[1]), "r"(a[2]), "r"(a[3]), "r"(b0), "r"(b1));
}
__device__ __forceinline__ uint32_t swz64(uint32_t off) {
    return off ^ ((off >> 3) & 0x30);
}
__device__ __forceinline__ uint32_t packbf2(__nv_bfloat16 a, __nv_bfloat16 b) {
    __nv_bfloat162 t; t.x = a; t.y = b;
    return *(uint32_t*)&t;
}
__device__ __forceinline__ unsigned enc(float f) {
    unsigned u = __float_as_uint(f);
    return (u & 0x80000000u) ? ~u : (u | 0x80000000u);
}
__device__ __forceinline__ float dec(unsigned x) {
    return (x & 0x80000000u) ? __uint_as_float(x & 0x7FFFFFFFu)
                             : __uint_as_float(~x);
}

// ------------------------------------------------------------ split + sumsq
__global__ void splitA_kernel(const float* __restrict__ z)
{
    int i = blockIdx.x * 256 + threadIdx.x;     // over MDIM*128
    int m = i >> 7, kc = (i & 127) << 2;
    float4 v = *(const float4*)(z + (size_t)m * KDIM + kc);
    uint2 H;
    H.x = packbf2(__float2bfloat16(v.x), __float2bfloat16(v.y));
    H.y = packbf2(__float2bfloat16(v.z), __float2bfloat16(v.w));
    *(uint2*)(g_Ah + (size_t)m * KDIM + kc) = H;
    float s = v.x * v.x + v.y * v.y + v.z * v.z + v.w * v.w;
    #pragma unroll
    for (int o = 16; o; o >>= 1) s += __shfl_down_sync(0xffffffffu, s, o);
    __shared__ float ws[8];
    int t = threadIdx.x;
    if ((t & 31) == 0) ws[t >> 5] = s;
    __syncthreads();
    if (t == 0)   g_zsq[m] = ws[0] + ws[1] + ws[2] + ws[3];
    if (t == 128) g_zsq[m] = ws[4] + ws[5] + ws[6] + ws[7];
}
__global__ void splitB_kernel(const float* __restrict__ cb)
{
    int i = blockIdx.x * 256 + threadIdx.x;     // over NDIM*128
    int n = i >> 7, kc = (i & 127) << 2;
    float4 v = *(const float4*)(cb + (size_t)n * KDIM + kc);
    uint2 H;
    H.x = packbf2(__float2bfloat16(v.x), __float2bfloat16(v.y));
    H.y = packbf2(__float2bfloat16(v.z), __float2bfloat16(v.w));
    *(uint2*)(g_Bh + (size_t)n * KDIM + kc) = H;
    float s = v.x * v.x + v.y * v.y + v.z * v.z + v.w * v.w;
    #pragma unroll
    for (int o = 16; o; o >>= 1) s += __shfl_down_sync(0xffffffffu, s, o);
    __shared__ float ws[8];
    int t = threadIdx.x;
    if ((t & 31) == 0) ws[t >> 5] = s;
    __syncthreads();
    if (t == 0)   g_esq[n] = ws[0] + ws[1] + ws[2] + ws[3];
    if (t == 128) g_esq[n] = ws[4] + ws[5] + ws[6] + ws[7];
}

// ------------------------------------------------------------ hi-only GEMM
__global__ __launch_bounds__(256, 2)
void gemm_hmma_kernel()
{
    extern __shared__ char smem[];
    __shared__ float s_esq[BN];
    const uint32_t smb = smem_u32(smem);
    const int tid = threadIdx.x;
    const int lane = tid & 31, warp = tid >> 5;
    const int m0 = blockIdx.y * BM;
    const int n0 = blockIdx.x * BN;

    // cp.async chunk descriptors: each 8KB region = 2 chunks/thread
    uint32_t swo[2];
    const __nv_bfloat16 *sAh[2], *sBh[2];
    #pragma unroll
    for (int r = 0; r < 2; r++) {
        int q = tid + r * 256, row = q >> 2, c = q & 3;
        swo[r] = swz64(row * 64 + c * 16);
        sAh[r] = g_Ah + (size_t)(m0 + row) * KDIM + c * 8;
        sBh[r] = g_Bh + (size_t)(n0 + row) * KDIM + c * 8;
    }

    #pragma unroll
    for (int s = 0; s < STAGES - 1; s++) {
        uint32_t bo = (uint32_t)s * STG;
        int k0 = s * BK;
        #pragma unroll
        for (int r = 0; r < 2; r++) {
            cp16(smb + bo + swo[r],        sAh[r] + k0);
            cp16(smb + bo + R_BH + swo[r], sBh[r] + k0);
        }
        asm volatile("cp.async.commit_group;" ::: "memory");
    }

    if (tid < BN) s_esq[tid] = g_esq[n0 + tid];

    float acc[4][4][4];
    #pragma unroll
    for (int i = 0; i < 4; i++)
        #pragma unroll
        for (int j = 0; j < 4; j++)
            #pragma unroll
            for (int q = 0; q < 4; q++) acc[i][j][q] = 0.f;

    const int wm = (warp & 1) * 64;       // 2 warps in M
    const int wn = (warp >> 1) * 32;      // 4 warps in N
    const uint32_t a_row = wm + (lane & 15);
    const uint32_t b_row = wn + (lane & 15);
    const uint32_t kchunk = (lane >> 4);

    for (int kt = 0; kt < NKT; kt++) {
        asm volatile("cp.async.wait_group %0;" :: "n"(STAGES - 2));
        __syncthreads();

        int pf = kt + STAGES - 1;
        if (pf < NKT) {
            uint32_t bo = (uint32_t)(pf % STAGES) * STG;
            int k0 = pf * BK;
            #pragma unroll
            for (int r = 0; r < 2; r++) {
                cp16(smb + bo + swo[r],        sAh[r] + k0);
                cp16(smb + bo + R_BH + swo[r], sBh[r] + k0);
            }
        }
        asm volatile("cp.async.commit_group;" ::: "memory");

        const uint32_t sA = smb + (uint32_t)(kt % STAGES) * STG;
        #pragma unroll
        for (int kk = 0; kk < 2; kk++) {
            const uint32_t kof = (kk * 2 + kchunk) * 16;
            uint32_t aH[4][4], b[2][4];
            #pragma unroll
            for (int i = 0; i < 4; i++)
                ldsm4(aH[i], sA + swz64((a_row + i * 16) * 64 + kof));
            #pragma unroll
            for (int p = 0; p < 2; p++)
                ldsm4(b[p], sA + R_BH + swz64((b_row + p * 16) * 64 + kof));
            #pragma unroll
            for (int i = 0; i < 4; i++)
                #pragma unroll
                for (int j = 0; j < 4; j++) {
                    int p = j >> 1, h = j & 1;
                    mma16816(acc[i][j], aH[i], b[p][h], b[p][h + 2]);
                }
        }
    }

    // ---- epilogue: approx dist' = esq - 2*acc (zsq constant per row:
    // irrelevant for within-row candidate selection). Per-16-code group keys.
    const int r0 = lane >> 2;
    const int gbase = (n0 >> 4) + (wn >> 4);
    #pragma unroll
    for (int i = 0; i < 4; i++) {
        int rowa = wm + i * 16 + r0;
        #pragma unroll
        for (int jp = 0; jp < 2; jp++) {
            unsigned long long bk0 = 0xFFFFFFFFFFFFFFFFull;
            unsigned long long bk1 = 0xFFFFFFFFFFFFFFFFull;
            #pragma unroll
            for (int jj = 0; jj < 2; jj++) {
                int j = jp * 2 + jj;
                int ncol = wn + j * 8 + 2 * (lane & 3);
                float e0 = s_esq[ncol], e1 = s_esq[ncol + 1];
                unsigned gn0 = (unsigned)(n0 + ncol), gn1 = gn0 + 1;
                float d; unsigned long long k;
                d = e0 - 2.0f * acc[i][j][0];
                k = ((unsigned long long)enc(d) << 32) | gn0; if (k < bk0) bk0 = k;
                d = e1 - 2.0f * acc[i][j][1];
                k = ((unsigned long long)enc(d) << 32) | gn1; if (k < bk0) bk0 = k;
                d = e0 - 2.0f * acc[i][j][2];
                k = ((unsigned long long)enc(d) << 32) | gn0; if (k < bk1) bk1 = k;
                d = e1 - 2.0f * acc[i][j][3];
                k = ((unsigned long long)enc(d) << 32) | gn1; if (k < bk1) bk1 = k;
            }
            #pragma unroll
            for (int o = 1; o <= 2; o <<= 1) {
                unsigned long long t0 = __shfl_xor_sync(0xffffffffu, bk0, o);
                unsigned long long t1 = __shfl_xor_sync(0xffffffffu, bk1, o);
                if (t0 < bk0) bk0 = t0;
                if (t1 < bk1) bk1 = t1;
            }
            if ((lane & 3) == 0) {
                g_gb[(size_t)(m0 + rowa) * NGRP + gbase + jp] = bk0;
                g_gb[(size_t)(m0 + rowa + 8) * NGRP + gbase + jp] = bk1;
            }
        }
    }
}

// ------------------------------------------------------------ refine (exact)
__global__ __launch_bounds__(256)
void refine_kernel(const float* __restrict__ z, const float* __restrict__ cb)
{
    const int lane = threadIdx.x & 31, wid = threadIdx.x >> 5;
    const int row = blockIdx.x * 8 + wid;
    const unsigned long long* keys = g_gb + (size_t)row * NGRP;

    // 1) row-min key
    unsigned long long kmin = 0xFFFFFFFFFFFFFFFFull;
    for (int g = lane; g < NGRP; g += 32) {
        unsigned long long k = keys[g];
        if (k < kmin) kmin = k;
    }
    #pragma unroll
    for (int o = 16; o; o >>= 1) {
        unsigned long long t = __shfl_xor_sync(0xffffffffu, kmin, o);
        if (t < kmin) kmin = t;
    }
    float th = dec((unsigned)(kmin >> 32)) + DELTA;

    // 2) collect flagged groups
    __shared__ int cnt[8];
    __shared__ short list[8][64];
    if (lane == 0) cnt[wid] = 0;
    __syncwarp();
    for (int g = lane; g < NGRP; g += 32) {
        if (dec((unsigned)(keys[g] >> 32)) <= th) {
            int p = atomicAdd(&cnt[wid], 1);
            if (p < 64) list[wid][p] = (short)g;
        }
    }
    __syncwarp();
    int nf = cnt[wid] < 64 ? cnt[wid] : 64;

    // 3) exact distances for flagged codes (reference form: (zs+esq)-2*dot)
    float zs = g_zsq[row];
    const float4* zr = (const float4*)(z + (size_t)row * KDIM) + (lane & 1) * 64;
    unsigned long long best = 0xFFFFFFFFFFFFFFFFull;
    for (int f = 0; f < nf; f++) {
        int g = list[wid][f];
        int code = g * 16 + (lane >> 1);       // 2 lanes per code
        const float4* cr = (const float4*)(cb + (size_t)code * KDIM) + (lane & 1) * 64;
        float dot = 0.f;
        #pragma unroll 8
        for (int k = 0; k < 64; k++) {
            float4 a = zr[k], b = cr[k];
            dot += a.x * b.x + a.y * b.y + a.z * b.z + a.w * b.w;
        }
        dot += __shfl_xor_sync(0xffffffffu, dot, 1);
        float d = (zs + g_esq[code]) - 2.0f * dot;
        unsigned long long key = ((unsigned long long)enc(d) << 32) | (unsigned)code;
        if (key < best) best = key;
    }
    #pragma unroll
    for (int o = 16; o; o >>= 1) {
        unsigned long long t = __shfl_xor_sync(0xffffffffu, best, o);
        if (t < best) best = t;
    }
    if (lane == 0) g_bestidx[row] = (unsigned)best;
}

// ------------------------------------------------------------ gather + loss
__global__ void gather_loss_kernel(const float* __restrict__ z,
                                   const float* __restrict__ cb,
                                   float* __restrict__ out_q,
                                   float* __restrict__ out_idx)
{
    int m = blockIdx.x;
    unsigned int idx = g_bestidx[m];
    const float4* zr = (const float4*)(z + (size_t)m * KDIM);
    const float4* cr = (const float4*)(cb + (size_t)idx * KDIM);
    float4* qr = (float4*)(out_q + (size_t)m * KDIM);
    float4 ze = zr[threadIdx.x];
    float4 cq = cr[threadIdx.x];
    float d0 = cq.x - ze.x, d1 = cq.y - ze.y, d2 = cq.z - ze.z, d3 = cq.w - ze.w;
    float4 o;
    o.x = ze.x + d0; o.y = ze.y + d1; o.z = ze.z + d2; o.w = ze.w + d3;
    qr[threadIdx.x] = o;
    float s = d0 * d0 + d1 * d1 + d2 * d2 + d3 * d3;
    #pragma unroll
    for (int off = 16; off; off >>= 1) s += __shfl_down_sync(0xffffffffu, s, off);
    __shared__ float ws[4];
    if ((threadIdx.x & 31) == 0) ws[threadIdx.x >> 5] = s;
    __syncthreads();
    if (threadIdx.x == 0) {
        g_partials[m] = ws[0] + ws[1] + ws[2] + ws[3];
        out_idx[m] = (float)idx;
    }
}

__global__ void loss_kernel(float* __restrict__ out_loss, int M, int K)
{
    __shared__ float sm[1024];
    float s = 0.f;
    for (int i = threadIdx.x; i < M; i += 1024) s += g_partials[i];
    sm[threadIdx.x] = s;
    __syncthreads();
    for (int o = 512; o; o >>= 1) {
        if (threadIdx.x < o) sm[threadIdx.x] += sm[threadIdx.x + o];
        __syncthreads();
    }
    if (threadIdx.x == 0) {
        float mean = sm[0] / ((float)M * (float)K);
        out_loss[0] = (mean + 0.25f * mean) / (float)K;
    }
}

// ------------------------------------------------------------ launch
extern "C" void kernel_launch(void* const* d_in, const int* in_sizes, int n_in,
                              void* d_out, int out_size)
{
    const float* z  = (const float*)d_in[0];
    const float* cb = (const float*)d_in[1];
    const int M = in_sizes[0] / KDIM;   // 32768
    const int N = in_sizes[1] / KDIM;   // 8192

    float* out      = (float*)d_out;
    float* out_q    = out;
    float* out_idx  = out + (size_t)M * KDIM;
    float* out_loss = out_idx + M;

    static int attr_done = 0;
    if (!attr_done) {
        cudaFuncSetAttribute(gemm_hmma_kernel,
                             cudaFuncAttributeMaxDynamicSharedMemorySize,
                             SMEM_DYN);
        attr_done = 1;
    }

    splitA_kernel<<<M * 128 / 256, 256>>>(z);
    splitB_kernel<<<N * 128 / 256, 256>>>(cb);

    dim3 grid(N / BN, M / BM);
    gemm_hmma_kernel<<<grid, 256, SMEM_DYN>>>();

    refine_kernel<<<M / 8, 256>>>(z, cb);
    gather_loss_kernel<<<M, 128>>>(z, cb, out_q, out_idx);
    loss_kernel<<<1, 1024>>>(out_loss, M, KDIM);
}